// round 16
// baseline (speedup 1.0000x reference)
#include <cuda_runtime.h>
#include <cuda_bf16.h>
#include <math.h>

// Problem constants
#define BB 256   // batch
#define SS 512   // seq len
#define HH 1024  // hidden
#define EE 256   // input dim
#define CC 128   // num classes

typedef unsigned int u32;

// ---------------- device scratch ----------------
__device__ float g_Gf[CC * HH];              // emb@Wfx^T + bf
__device__ float g_Gi[CC * HH];              // emb@Wix^T + bi
__device__ float g_Go[CC * HH];              // emb@Wox^T + bo
__device__ float g_Sc[CC * HH];              // sigmoid(emb@Wcx^T + bc)
__device__ __nv_bfloat16 g_cst[2][2][BB * HH];   // cell state [buf][hi/lo][b*HH+k]
__device__ __nv_bfloat16 g_Wsp[6][HH * HH];      // split weights [fh,fl,ih,il,oh,ol][n*HH+k]
__device__ float g_h[BB * HH];               // final hidden [b][h]

// ---------------- helpers ----------------
__device__ __forceinline__ float sigmoidf_(float x) {
    return 1.0f / (1.0f + __expf(-x));
}
__device__ __forceinline__ u32 smem_u32(const void* p) {
    return (u32)__cvta_generic_to_shared(p);
}
__device__ __forceinline__ void cpa16(u32 dst, const void* src) {
    asm volatile("cp.async.cg.shared.global [%0], [%1], 16;\n" :: "r"(dst), "l"(src));
}
#define CP_COMMIT() asm volatile("cp.async.commit_group;\n" ::: "memory")
#define CP_WAIT0()  asm volatile("cp.async.wait_group 0;\n" ::: "memory")
#define CP_WAIT1()  asm volatile("cp.async.wait_group 1;\n" ::: "memory")

__device__ __forceinline__ void ldsm4(u32& r0, u32& r1, u32& r2, u32& r3, u32 addr) {
    asm volatile("ldmatrix.sync.aligned.m8n8.x4.shared.b16 {%0,%1,%2,%3}, [%4];"
                 : "=r"(r0), "=r"(r1), "=r"(r2), "=r"(r3) : "r"(addr));
}
__device__ __forceinline__ void mma16816(float& d0, float& d1, float& d2, float& d3,
                                         u32 a0, u32 a1, u32 a2, u32 a3, u32 b0, u32 b1) {
    asm volatile("mma.sync.aligned.m16n8k16.row.col.f32.bf16.bf16.f32 "
                 "{%0,%1,%2,%3}, {%4,%5,%6,%7}, {%8,%9}, {%0,%1,%2,%3};"
                 : "+f"(d0), "+f"(d1), "+f"(d2), "+f"(d3)
                 : "r"(a0), "r"(a1), "r"(a2), "r"(a3), "r"(b0), "r"(b1));
}

// ---- step kernel smem geometry: M=32, K-tile = 128 (256B rows padded to 272B) ----
// Pure bf16-hi mainloop: A-hi (32 rows) + W {fh, ih} (32 rows each)
#define S_ROWB  272
#define S_W     8704             // 32*272 (A ends here)
#define S_WS    8704             // 32*272 per W array
#define S_BUF   26112            // A(8704) + W(2*8704)
#define SMEM_STEP (3 * S_BUF)    // 78336 (3-stage)

// ---- final_o kernel smem geometry: K-tile = 64 (128B rows padded to 144B) ----
#define ROWF     144
#define F_ALO    9216
#define F_W      18432
#define F_WS     4608
#define F_BUF    27648
#define SMEM_FIN (2 * F_BUF)

// ---------------- kernel: zero initial cell state ----------------
#define CZ_FLOAT4 ((int)(sizeof(g_cst[0]) / sizeof(float4)))
__global__ void zero_kernel() {
    int i = blockIdx.x * blockDim.x + threadIdx.x;
    if (i < CZ_FLOAT4)
        reinterpret_cast<float4*>(g_cst[0])[i] = make_float4(0.f, 0.f, 0.f, 0.f);
}

// ---------------- kernel: split recurrent weights into bf16 hi/lo ----------------
__global__ __launch_bounds__(256)
void wsplit_kernel(const float* __restrict__ Wf, const float* __restrict__ Wi,
                   const float* __restrict__ Wo) {
    const int i = blockIdx.x * 256 + threadIdx.x;
    if (i >= HH * HH) return;
    {
        const float w = Wf[i];
        const __nv_bfloat16 h = __float2bfloat16(w);
        g_Wsp[0][i] = h;
        g_Wsp[1][i] = __float2bfloat16(w - __bfloat162float(h));
    }
    {
        const float w = Wi[i];
        const __nv_bfloat16 h = __float2bfloat16(w);
        g_Wsp[2][i] = h;
        g_Wsp[3][i] = __float2bfloat16(w - __bfloat162float(h));
    }
    {
        const float w = Wo[i];
        const __nv_bfloat16 h = __float2bfloat16(w);
        g_Wsp[4][i] = h;
        g_Wsp[5][i] = __float2bfloat16(w - __bfloat162float(h));
    }
}

// ---------------- kernel: precompute class->gate tables ----------------
__global__ __launch_bounds__(256)
void tab_kernel(const float* __restrict__ emb,
                const float* __restrict__ Wfx, const float* __restrict__ Wix,
                const float* __restrict__ Wox, const float* __restrict__ Wcx,
                const float* __restrict__ bf,  const float* __restrict__ bi,
                const float* __restrict__ bo,  const float* __restrict__ bc) {
    __shared__ float es[32][33];
    __shared__ float ws[4][32][33];

    const int tid = threadIdx.x;
    const int h0  = blockIdx.x * 32;
    const int c0b = blockIdx.y * 32;
    const int tx  = tid & 31;
    const int ty  = tid >> 5;

    float acc[4][4];
#pragma unroll
    for (int m = 0; m < 4; m++)
#pragma unroll
        for (int q = 0; q < 4; q++) acc[m][q] = 0.f;

    for (int k0 = 0; k0 < EE; k0 += 32) {
        __syncthreads();
        const int ccol  = tid & 31;
        const int rbase = tid >> 5;
#pragma unroll
        for (int rr = 0; rr < 4; rr++) {
            const int r = rbase + rr * 8;
            es[r][ccol]    = emb[(c0b + r) * EE + k0 + ccol];
            ws[0][r][ccol] = Wfx[(h0 + r) * EE + k0 + ccol];
            ws[1][r][ccol] = Wix[(h0 + r) * EE + k0 + ccol];
            ws[2][r][ccol] = Wox[(h0 + r) * EE + k0 + ccol];
            ws[3][r][ccol] = Wcx[(h0 + r) * EE + k0 + ccol];
        }
        __syncthreads();
#pragma unroll
        for (int kk = 0; kk < 32; kk++) {
            const float b0 = ws[0][tx][kk];
            const float b1 = ws[1][tx][kk];
            const float b2 = ws[2][tx][kk];
            const float b3 = ws[3][tx][kk];
#pragma unroll
            for (int q = 0; q < 4; q++) {
                const float a = es[ty + q * 8][kk];
                acc[0][q] = fmaf(a, b0, acc[0][q]);
                acc[1][q] = fmaf(a, b1, acc[1][q]);
                acc[2][q] = fmaf(a, b2, acc[2][q]);
                acc[3][q] = fmaf(a, b3, acc[3][q]);
            }
        }
    }

    const int h = h0 + tx;
    const float vbf = bf[h], vbi = bi[h], vbo = bo[h], vbc = bc[h];
#pragma unroll
    for (int q = 0; q < 4; q++) {
        const int cls = c0b + ty + q * 8;
        g_Gf[cls * HH + h] = acc[0][q] + vbf;
        g_Gi[cls * HH + h] = acc[1][q] + vbi;
        g_Go[cls * HH + h] = acc[2][q] + vbo;
        g_Sc[cls * HH + h] = sigmoidf_(acc[3][q] + vbc);
    }
}

// ---------------- kernel: one recurrence step ----------------
// Pure bf16-hi MMA (AhBh only). Tile M=32 x N=32, 128 threads = 4 warps
// (2m x 2n, warp tile m16n16). K-tile 128, 3-stage cp.async pipeline,
// register double-buffered fragments. Grid (32 n, 8 m) = 256 blocks
// -> 2 blocks/SM co-resident so barrier bubbles overlap across blocks.
__global__ __launch_bounds__(128)
void step_kernel(const int* __restrict__ x, int t) {
    const __nv_bfloat16* __restrict__ cih = g_cst[t & 1][0];
    const __nv_bfloat16* __restrict__ cil = g_cst[t & 1][1];
    __nv_bfloat16* __restrict__ coh = g_cst[(t & 1) ^ 1][0];
    __nv_bfloat16* __restrict__ clo = g_cst[(t & 1) ^ 1][1];

    extern __shared__ __align__(16) char dynsm[];
    __shared__ int cls_s[32];

    const int tid = threadIdx.x;
    const int M0  = blockIdx.y * 32;
    const int N0  = blockIdx.x * 32;
    if (tid < 32) cls_s[tid] = x[(M0 + tid) * SS + t];

    const int l   = tid & 31;
    const int wid = tid >> 5;       // 0..3
    const int wm  = wid >> 1;       // 0..1
    const int wn  = wid & 1;        // 0..1

    const u32 sm0 = smem_u32(dynsm);

    // ---- cp.async tile loader (~25KB per tile, 12 cpa16/thread) ----
    auto load_tile = [&](int kt, u32 bb) {
        const int k0 = kt * 128;
#pragma unroll
        for (int j = 0; j < 4; j++) {               // A hi: 32 rows x 16 chunks
            const int idx = tid + j * 128;          // 0..511
            const int row = idx >> 4, c16 = idx & 15;
            cpa16(bb + row * S_ROWB + c16 * 16,
                  cih + (size_t)(M0 + row) * HH + k0 + c16 * 8);
        }
#pragma unroll
        for (int j = 0; j < 8; j++) {               // W: {fh, ih} x 32 rows x 16 chunks
            const int idx = tid + j * 128;          // 0..1023
            const int arr = idx >> 9, row = (idx >> 4) & 31, c16 = idx & 15;
            const u32 off = S_W + arr * S_WS + row * S_ROWB + c16 * 16;
            cpa16(bb + off, g_Wsp[arr * 2] + (size_t)(N0 + row) * HH + k0 + c16 * 8);
        }
    };

    // prefetch tiles 0 and 1 (separate groups)
    load_tile(0, sm0);             CP_COMMIT();
    load_tile(1, sm0 + S_BUF);     CP_COMMIT();

    __syncthreads();   // cls_s visible

    // ---- hoisted epilogue operands ----
    const int qr = l >> 2;
    const int qc = (l & 3) * 2;
    float hGf[8], hGi[8], hSc[8], hCo[8];
#pragma unroll
    for (int p = 0; p < 8; p++) {
        const int j  = p >> 2;
        const int r  = (p >> 1) & 1;
        const int cc = p & 1;
        const int bl = wm * 16 + qr + r * 8;
        const int b  = M0 + bl;
        const int n  = N0 + wn * 16 + j * 8 + qc + cc;
        const int cls = cls_s[bl];
        hGf[p] = __ldg(&g_Gf[cls * HH + n]);
        hGi[p] = __ldg(&g_Gi[cls * HH + n]);
        hSc[p] = __ldg(&g_Sc[cls * HH + n]);
        hCo[p] = __bfloat162float(__ldg(&cih[(size_t)b * HH + n]))
               + __bfloat162float(__ldg(&cil[(size_t)b * HH + n]));
    }

    // ---- ldmatrix base addresses ----
    const u32 abase = sm0 + (wm * 16 + (l & 15)) * S_ROWB + ((l >> 4) & 1) * 16;
    const u32 wbase = sm0 + S_W
                    + ((l & 7) + ((l & 16) ? 8 : 0) + wn * 16) * S_ROWB
                    + ((l & 8) ? 16 : 0);

    float fah[8], iah[8];
#pragma unroll
    for (int p = 0; p < 8; p++) { fah[p] = 0.f; iah[p] = 0.f; }

    // double-buffered fragment registers
    u32 AH[2][4], Fh[2][4], Ih[2][4];

#define LDFR(kc_, s_)                                                         \
    do {                                                                      \
        const u32 ko_ = (kc_) * 32;                                           \
        ldsm4(AH[s_][0], AH[s_][1], AH[s_][2], AH[s_][3], ab + ko_);          \
        ldsm4(Fh[s_][0], Fh[s_][1], Fh[s_][2], Fh[s_][3], wb + ko_);          \
        ldsm4(Ih[s_][0], Ih[s_][1], Ih[s_][2], Ih[s_][3], wb + S_WS + ko_);   \
    } while (0)

#define MMASET(s_)                                                            \
    do {                                                                      \
        mma16816(fah[0], fah[1], fah[2], fah[3],                              \
                 AH[s_][0], AH[s_][1], AH[s_][2], AH[s_][3], Fh[s_][0], Fh[s_][1]); \
        mma16816(fah[4], fah[5], fah[6], fah[7],                              \
                 AH[s_][0], AH[s_][1], AH[s_][2], AH[s_][3], Fh[s_][2], Fh[s_][3]); \
        mma16816(iah[0], iah[1], iah[2], iah[3],                              \
                 AH[s_][0], AH[s_][1], AH[s_][2], AH[s_][3], Ih[s_][0], Ih[s_][1]); \
        mma16816(iah[4], iah[5], iah[6], iah[7],                              \
                 AH[s_][0], AH[s_][1], AH[s_][2], AH[s_][3], Ih[s_][2], Ih[s_][3]); \
    } while (0)

#pragma unroll 1
    for (int it = 0; it < 8; it++) {
        const int buf = it % 3;
        if (it < 7) { CP_WAIT1(); } else { CP_WAIT0(); }
        __syncthreads();          // tile `it` resident; prior tile's readers done

        if (it + 2 < 8) {         // prefetch tile it+2 into buffer (it+2)%3
            load_tile(it + 2, sm0 + (u32)((it + 2) % 3) * S_BUF);
            CP_COMMIT();
        }

        const u32 ab = abase + (u32)buf * S_BUF;
        const u32 wb = wbase + (u32)buf * S_BUF;

        LDFR(0, 0);
#pragma unroll
        for (int kc = 0; kc < 8; kc++) {
            const int s = kc & 1;
            if (kc < 7) LDFR(kc + 1, s ^ 1);
            MMASET(s);
        }
    }

    // ---- epilogue: gates + cell update + re-split ----
#pragma unroll
    for (int p = 0; p < 8; p++) {
        const int j  = p >> 2;
        const int r  = (p >> 1) & 1;
        const int cc = p & 1;
        const int b  = M0 + wm * 16 + qr + r * 8;
        const int n  = N0 + wn * 16 + j * 8 + qc + cc;
        const int idx = j * 4 + r * 2 + cc;
        const float f  = sigmoidf_(fah[idx] + hGf[p]);
        const float ii = sigmoidf_(iah[idx] + hGi[p]);
        const float cn = hSc[p] * ii + hCo[p] * f;
        const __nv_bfloat16 hh = __float2bfloat16(cn);
        coh[(size_t)b * HH + n] = hh;
        clo[(size_t)b * HH + n] = __float2bfloat16(cn - __bfloat162float(hh));
    }
#undef LDFR
#undef MMASET
}

// ---------------- kernel: final o-gate + hidden (runs once; full 3-term) ----------------
__global__ __launch_bounds__(256)
void final_o_kernel(const int* __restrict__ x) {
    const __nv_bfloat16* __restrict__ cih = g_cst[1][0];   // c_prev (written t=510)
    const __nv_bfloat16* __restrict__ cil = g_cst[1][1];
    const __nv_bfloat16* __restrict__ lih = g_cst[0][0];   // c_last (written t=511)
    const __nv_bfloat16* __restrict__ lil = g_cst[0][1];

    extern __shared__ __align__(16) char dynsm[];
    __shared__ int cls_s[64];

    const int tid = threadIdx.x;
    const int M0  = blockIdx.y * 64;
    const int N0  = blockIdx.x * 32;
    if (tid < 64) cls_s[tid] = x[(M0 + tid) * SS + (SS - 1)];

    const int l   = tid & 31;
    const int wid = tid >> 5;
    const int wm  = wid >> 1;
    const int wn  = wid & 1;

    const int ar0 = tid >> 3;
    const int ar1 = (tid + 256) >> 3;
    const int ao  = tid & 7;
    const size_t sA0 = (size_t)(M0 + ar0) * HH + ao * 8;
    const size_t sA1 = (size_t)(M0 + ar1) * HH + ao * 8;
    const u32 dA0 = ar0 * ROWF + ao * 16;
    const u32 dA1 = ar1 * ROWF + ao * 16;
    const int wrow = tid >> 3;
    const size_t sW = (size_t)(N0 + wrow) * HH + ao * 8;
    const u32 dW = wrow * ROWF + ao * 16;

    const u32 sm0 = smem_u32(dynsm);

    cpa16(sm0 + dA0,         cih + sA0);
    cpa16(sm0 + dA1,         cih + sA1);
    cpa16(sm0 + F_ALO + dA0, cil + sA0);
    cpa16(sm0 + F_ALO + dA1, cil + sA1);
    cpa16(sm0 + F_W + dW,        g_Wsp[4] + sW);
    cpa16(sm0 + F_W + F_WS + dW, g_Wsp[5] + sW);
    CP_COMMIT();

    __syncthreads();

    const int qr = l >> 2;
    const int qc = (l & 3) * 2;
    float hGo[8], hCl[8];
#pragma unroll
    for (int p = 0; p < 8; p++) {
        const int j  = p >> 2;
        const int r  = (p >> 1) & 1;
        const int cc = p & 1;
        const int bl = wm * 16 + qr + r * 8;
        const int b  = M0 + bl;
        const int n  = N0 + wn * 16 + j * 8 + qc + cc;
        const int cls = cls_s[bl];
        hGo[p] = __ldg(&g_Go[cls * HH + n]);
        hCl[p] = __bfloat162float(__ldg(&lih[(size_t)b * HH + n]))
               + __bfloat162float(__ldg(&lil[(size_t)b * HH + n]));
    }

    const u32 abase = sm0 + (wm * 16 + (l & 15)) * ROWF + ((l >> 4) & 1) * 16;
    const u32 wbase = sm0 + F_W
                    + ((l & 7) + ((l & 16) ? 8 : 0) + wn * 16) * ROWF
                    + ((l & 8) ? 16 : 0);

    float oa[8];
#pragma unroll
    for (int p = 0; p < 8; p++) oa[p] = 0.f;

#pragma unroll 1
    for (int it = 0; it < 16; it++) {
        const int buf = it & 1;
        CP_WAIT0();
        __syncthreads();
        if (it < 15) {
            const size_t kadv = (size_t)(it + 1) * 64;
            const u32 db = (buf ^ 1) * F_BUF;
            cpa16(sm0 + db + dA0,         cih + sA0 + kadv);
            cpa16(sm0 + db + dA1,         cih + sA1 + kadv);
            cpa16(sm0 + db + F_ALO + dA0, cil + sA0 + kadv);
            cpa16(sm0 + db + F_ALO + dA1, cil + sA1 + kadv);
            cpa16(sm0 + db + F_W + dW,        g_Wsp[4] + sW + kadv);
            cpa16(sm0 + db + F_W + F_WS + dW, g_Wsp[5] + sW + kadv);
            CP_COMMIT();
        }

        const u32 ab = abase + buf * F_BUF;
        const u32 wb = wbase + buf * F_BUF;
#pragma unroll
        for (int kc = 0; kc < 4; kc++) {
            const u32 ko = kc * 32;
            u32 ah0, ah1, ah2, ah3, al0, al1, al2, al3;
            ldsm4(ah0, ah1, ah2, ah3, ab + ko);
            ldsm4(al0, al1, al2, al3, ab + F_ALO + ko);
            u32 o0, o1, o2, o3, q0, q1, q2, q3;
            ldsm4(o0, o1, o2, o3, wb + ko);
            ldsm4(q0, q1, q2, q3, wb + F_WS + ko);
            mma16816(oa[0], oa[1], oa[2], oa[3], ah0, ah1, ah2, ah3, o0, o1);
            mma16816(oa[0], oa[1], oa[2], oa[3], ah0, ah1, ah2, ah3, q0, q1);
            mma16816(oa[0], oa[1], oa[2], oa[3], al0, al1, al2, al3, o0, o1);
            mma16816(oa[4], oa[5], oa[6], oa[7], ah0, ah1, ah2, ah3, o2, o3);
            mma16816(oa[4], oa[5], oa[6], oa[7], ah0, ah1, ah2, ah3, q2, q3);
            mma16816(oa[4], oa[5], oa[6], oa[7], al0, al1, al2, al3, o2, o3);
        }
    }

#pragma unroll
    for (int p = 0; p < 8; p++) {
        const int j  = p >> 2;
        const int r  = (p >> 1) & 1;
        const int cc = p & 1;
        const int b  = M0 + wm * 16 + qr + r * 8;
        const int n  = N0 + wn * 16 + j * 8 + qc + cc;
        const int idx = j * 4 + r * 2 + cc;
        const float o = sigmoidf_(oa[idx] + hGo[p]);
        g_h[(size_t)b * HH + n] = tanhf(hCl[p]) * o;
    }
}

// ---------------- kernel: logits + log_softmax ----------------
__global__ __launch_bounds__(128)
void logits_kernel(const float* __restrict__ Wph, const float* __restrict__ bp,
                   float* __restrict__ out) {
    const int b = blockIdx.x;
    const int j = threadIdx.x;

    __shared__ __align__(16) float h_s[HH];
    __shared__ float red[128];

    const float4* hv  = reinterpret_cast<const float4*>(&g_h[(size_t)b * HH]);
    float4*       hs4 = reinterpret_cast<float4*>(h_s);
    for (int i = j; i < HH / 4; i += 128) hs4[i] = hv[i];
    __syncthreads();

    float acc = 0.f;
    const float4* w4 = reinterpret_cast<const float4*>(&Wph[(size_t)j * HH]);
#pragma unroll 4
    for (int k = 0; k < HH / 4; k++) {
        const float4 w = w4[k];
        const float4 h = hs4[k];
        acc = fmaf(h.x, w.x, acc);
        acc = fmaf(h.y, w.y, acc);
        acc = fmaf(h.z, w.z, acc);
        acc = fmaf(h.w, w.w, acc);
    }
    const float p = acc + bp[j];

    red[j] = p;
    __syncthreads();
    for (int s2 = 64; s2 > 0; s2 >>= 1) {
        if (j < s2) red[j] = fmaxf(red[j], red[j + s2]);
        __syncthreads();
    }
    const float mx = red[0];
    __syncthreads();
    red[j] = expf(p - mx);
    __syncthreads();
    for (int s2 = 64; s2 > 0; s2 >>= 1) {
        if (j < s2) red[j] += red[j + s2];
        __syncthreads();
    }
    const float lse = logf(red[0]) + mx;
    out[b * CC + j] = p - lse;
}

// ---------------- launcher ----------------
extern "C" void kernel_launch(void* const* d_in, const int* in_sizes, int n_in,
                              void* d_out, int out_size) {
    const int*   x   = (const int*)  d_in[0];
    const float* emb = (const float*)d_in[1];
    const float* Wcx = (const float*)d_in[2];
    const float* bc  = (const float*)d_in[3];
    const float* Wix = (const float*)d_in[4];
    const float* Wih = (const float*)d_in[5];
    const float* bi  = (const float*)d_in[6];
    const float* Wfx = (const float*)d_in[7];
    const float* Wfh = (const float*)d_in[8];
    const float* bf  = (const float*)d_in[9];
    const float* Wox = (const float*)d_in[10];
    const float* Woh = (const float*)d_in[11];
    const float* bo  = (const float*)d_in[12];
    const float* Wph = (const float*)d_in[13];
    const float* bp  = (const float*)d_in[14];
    float* out = (float*)d_out;

    cudaFuncSetAttribute(step_kernel,
                         cudaFuncAttributeMaxDynamicSharedMemorySize, SMEM_STEP);
    cudaFuncSetAttribute(final_o_kernel,
                         cudaFuncAttributeMaxDynamicSharedMemorySize, SMEM_FIN);

    wsplit_kernel<<<(HH * HH + 255) / 256, 256>>>(Wfh, Wih, Woh);
    tab_kernel<<<dim3(32, 4), 256>>>(emb, Wfx, Wix, Wox, Wcx, bf, bi, bo, bc);

    const int zgrid = (CZ_FLOAT4 + 255) / 256;
    zero_kernel<<<zgrid, 256>>>();

    for (int t = 0; t < SS; t++) {
        step_kernel<<<dim3(32, 8), 128, SMEM_STEP>>>(x, t);
    }

    final_o_kernel<<<dim3(32, 4), 256, SMEM_FIN>>>(x);
    logits_kernel<<<BB, 128>>>(Wph, bp, out);
}

// round 17
// speedup vs baseline: 1.0868x; 1.0868x over previous
#include <cuda_runtime.h>
#include <cuda_bf16.h>
#include <math.h>

// Problem constants
#define BB 256   // batch
#define SS 512   // seq len
#define HH 1024  // hidden
#define EE 256   // input dim
#define CC 128   // num classes

typedef unsigned int u32;

// ---------------- device scratch ----------------
__device__ float g_Gf[CC * HH];              // emb@Wfx^T + bf
__device__ float g_Gi[CC * HH];              // emb@Wix^T + bi
__device__ float g_Go[CC * HH];              // emb@Wox^T + bo
__device__ float g_Sc[CC * HH];              // sigmoid(emb@Wcx^T + bc)
__device__ __nv_bfloat16 g_cst[2][2][BB * HH];   // cell state [buf][hi/lo][b*HH+k]
__device__ __nv_bfloat16 g_Wsp[6][HH * HH];      // split weights [fh,fl,ih,il,oh,ol][n*HH+k]
__device__ float g_h[BB * HH];               // final hidden [b][h]

// ---------------- helpers ----------------
__device__ __forceinline__ float sigmoidf_(float x) {
    return 1.0f / (1.0f + __expf(-x));
}
__device__ __forceinline__ u32 smem_u32(const void* p) {
    return (u32)__cvta_generic_to_shared(p);
}
__device__ __forceinline__ void cpa16(u32 dst, const void* src) {
    asm volatile("cp.async.cg.shared.global [%0], [%1], 16;\n" :: "r"(dst), "l"(src));
}
#define CP_COMMIT() asm volatile("cp.async.commit_group;\n" ::: "memory")
#define CP_WAIT0()  asm volatile("cp.async.wait_group 0;\n" ::: "memory")

__device__ __forceinline__ void ldsm4(u32& r0, u32& r1, u32& r2, u32& r3, u32 addr) {
    asm volatile("ldmatrix.sync.aligned.m8n8.x4.shared.b16 {%0,%1,%2,%3}, [%4];"
                 : "=r"(r0), "=r"(r1), "=r"(r2), "=r"(r3) : "r"(addr));
}
__device__ __forceinline__ void mma16816(float& d0, float& d1, float& d2, float& d3,
                                         u32 a0, u32 a1, u32 a2, u32 a3, u32 b0, u32 b1) {
    asm volatile("mma.sync.aligned.m16n8k16.row.col.f32.bf16.bf16.f32 "
                 "{%0,%1,%2,%3}, {%4,%5,%6,%7}, {%8,%9}, {%0,%1,%2,%3};"
                 : "+f"(d0), "+f"(d1), "+f"(d2), "+f"(d3)
                 : "r"(a0), "r"(a1), "r"(a2), "r"(a3), "r"(b0), "r"(b1));
}

// ---- step kernel smem geometry: M=64, K-tile = 256 (512B rows padded to 528B) ----
// Pure bf16-hi mainloop: A-hi (64 rows) + W {fh, ih} (32 rows each)
#define S_ROWB  528
#define S_W     33792            // 64*528 (A ends here)
#define S_WS    16896            // 32*528 per W array
#define S_BUF   67584            // A(33792) + W(2*16896)
#define SMEM_STEP (2 * S_BUF)    // 135168

// ---- final_o kernel smem geometry: K-tile = 64 (128B rows padded to 144B) ----
#define ROWF     144
#define F_ALO    9216
#define F_W      18432
#define F_WS     4608
#define F_BUF    27648
#define SMEM_FIN (2 * F_BUF)

// ---------------- kernel: zero initial cell state ----------------
#define CZ_FLOAT4 ((int)(sizeof(g_cst[0]) / sizeof(float4)))
__global__ void zero_kernel() {
    int i = blockIdx.x * blockDim.x + threadIdx.x;
    if (i < CZ_FLOAT4)
        reinterpret_cast<float4*>(g_cst[0])[i] = make_float4(0.f, 0.f, 0.f, 0.f);
}

// ---------------- kernel: split recurrent weights into bf16 hi/lo ----------------
__global__ __launch_bounds__(256)
void wsplit_kernel(const float* __restrict__ Wf, const float* __restrict__ Wi,
                   const float* __restrict__ Wo) {
    const int i = blockIdx.x * 256 + threadIdx.x;
    if (i >= HH * HH) return;
    {
        const float w = Wf[i];
        const __nv_bfloat16 h = __float2bfloat16(w);
        g_Wsp[0][i] = h;
        g_Wsp[1][i] = __float2bfloat16(w - __bfloat162float(h));
    }
    {
        const float w = Wi[i];
        const __nv_bfloat16 h = __float2bfloat16(w);
        g_Wsp[2][i] = h;
        g_Wsp[3][i] = __float2bfloat16(w - __bfloat162float(h));
    }
    {
        const float w = Wo[i];
        const __nv_bfloat16 h = __float2bfloat16(w);
        g_Wsp[4][i] = h;
        g_Wsp[5][i] = __float2bfloat16(w - __bfloat162float(h));
    }
}

// ---------------- kernel: precompute class->gate tables ----------------
__global__ __launch_bounds__(256)
void tab_kernel(const float* __restrict__ emb,
                const float* __restrict__ Wfx, const float* __restrict__ Wix,
                const float* __restrict__ Wox, const float* __restrict__ Wcx,
                const float* __restrict__ bf,  const float* __restrict__ bi,
                const float* __restrict__ bo,  const float* __restrict__ bc) {
    __shared__ float es[32][33];
    __shared__ float ws[4][32][33];

    const int tid = threadIdx.x;
    const int h0  = blockIdx.x * 32;
    const int c0b = blockIdx.y * 32;
    const int tx  = tid & 31;
    const int ty  = tid >> 5;

    float acc[4][4];
#pragma unroll
    for (int m = 0; m < 4; m++)
#pragma unroll
        for (int q = 0; q < 4; q++) acc[m][q] = 0.f;

    for (int k0 = 0; k0 < EE; k0 += 32) {
        __syncthreads();
        const int ccol  = tid & 31;
        const int rbase = tid >> 5;
#pragma unroll
        for (int rr = 0; rr < 4; rr++) {
            const int r = rbase + rr * 8;
            es[r][ccol]    = emb[(c0b + r) * EE + k0 + ccol];
            ws[0][r][ccol] = Wfx[(h0 + r) * EE + k0 + ccol];
            ws[1][r][ccol] = Wix[(h0 + r) * EE + k0 + ccol];
            ws[2][r][ccol] = Wox[(h0 + r) * EE + k0 + ccol];
            ws[3][r][ccol] = Wcx[(h0 + r) * EE + k0 + ccol];
        }
        __syncthreads();
#pragma unroll
        for (int kk = 0; kk < 32; kk++) {
            const float b0 = ws[0][tx][kk];
            const float b1 = ws[1][tx][kk];
            const float b2 = ws[2][tx][kk];
            const float b3 = ws[3][tx][kk];
#pragma unroll
            for (int q = 0; q < 4; q++) {
                const float a = es[ty + q * 8][kk];
                acc[0][q] = fmaf(a, b0, acc[0][q]);
                acc[1][q] = fmaf(a, b1, acc[1][q]);
                acc[2][q] = fmaf(a, b2, acc[2][q]);
                acc[3][q] = fmaf(a, b3, acc[3][q]);
            }
        }
    }

    const int h = h0 + tx;
    const float vbf = bf[h], vbi = bi[h], vbo = bo[h], vbc = bc[h];
#pragma unroll
    for (int q = 0; q < 4; q++) {
        const int cls = c0b + ty + q * 8;
        g_Gf[cls * HH + h] = acc[0][q] + vbf;
        g_Gi[cls * HH + h] = acc[1][q] + vbi;
        g_Go[cls * HH + h] = acc[2][q] + vbo;
        g_Sc[cls * HH + h] = sigmoidf_(acc[3][q] + vbc);
    }
}

// ---------------- kernel: one recurrence step ----------------
// Pure bf16-hi MMA (AhBh only): 4 MMAs/kc, 3 LDSM/kc.
// 256 threads = 8 warps (4m x 2n), warp tile m16n16, K-tile 256 (4 tiles/step),
// 2-stage smem pipeline + register double-buffered fragments.
// Cell state stays hi+lo in gmem: the c*f recurrence path remains near-exact.
__global__ __launch_bounds__(256)
void step_kernel(const int* __restrict__ x, int t) {
    const __nv_bfloat16* __restrict__ cih = g_cst[t & 1][0];
    const __nv_bfloat16* __restrict__ cil = g_cst[t & 1][1];
    __nv_bfloat16* __restrict__ coh = g_cst[(t & 1) ^ 1][0];
    __nv_bfloat16* __restrict__ clo = g_cst[(t & 1) ^ 1][1];

    extern __shared__ __align__(16) char dynsm[];
    __shared__ int cls_s[64];

    const int tid = threadIdx.x;
    const int M0  = blockIdx.y * 64;
    const int N0  = blockIdx.x * 32;
    if (tid < 64) cls_s[tid] = x[(M0 + tid) * SS + t];

    const int l   = tid & 31;
    const int wid = tid >> 5;
    const int wm  = wid >> 1;       // 0..3
    const int wn  = wid & 1;        // 0..1

    const u32 sm0 = smem_u32(dynsm);

    // ---- cp.async tile loader (64KB per tile, 16 cpa16/thread) ----
    auto load_tile = [&](int kt, u32 bb) {
        const int k0 = kt * 256;
#pragma unroll
        for (int j = 0; j < 8; j++) {               // A hi: 64 rows x 32 chunks
            const int idx = tid + j * 256;          // 0..2047
            const int row = idx >> 5, c16 = idx & 31;
            cpa16(bb + row * S_ROWB + c16 * 16,
                  cih + (size_t)(M0 + row) * HH + k0 + c16 * 8);
        }
#pragma unroll
        for (int j = 0; j < 8; j++) {               // W: {fh, ih} x 32 rows x 32 chunks
            const int idx = tid + j * 256;          // 0..2047
            const int arr = idx >> 10, row = (idx >> 5) & 31, c16 = idx & 31;
            const u32 off = S_W + arr * S_WS + row * S_ROWB + c16 * 16;
            cpa16(bb + off, g_Wsp[arr * 2] + (size_t)(N0 + row) * HH + k0 + c16 * 8);
        }
    };

    // prefetch tile 0
    load_tile(0, sm0);
    CP_COMMIT();

    __syncthreads();   // cls_s visible

    // ---- hoisted epilogue operands ----
    const int qr = l >> 2;
    const int qc = (l & 3) * 2;
    float hGf[8], hGi[8], hSc[8], hCo[8];
#pragma unroll
    for (int p = 0; p < 8; p++) {
        const int j  = p >> 2;
        const int r  = (p >> 1) & 1;
        const int cc = p & 1;
        const int bl = wm * 16 + qr + r * 8;
        const int b  = M0 + bl;
        const int n  = N0 + wn * 16 + j * 8 + qc + cc;
        const int cls = cls_s[bl];
        hGf[p] = __ldg(&g_Gf[cls * HH + n]);
        hGi[p] = __ldg(&g_Gi[cls * HH + n]);
        hSc[p] = __ldg(&g_Sc[cls * HH + n]);
        hCo[p] = __bfloat162float(__ldg(&cih[(size_t)b * HH + n]))
               + __bfloat162float(__ldg(&cil[(size_t)b * HH + n]));
    }

    // ---- ldmatrix base addresses ----
    const u32 abase = sm0 + (wm * 16 + (l & 15)) * S_ROWB + ((l >> 4) & 1) * 16;
    const u32 wbase = sm0 + S_W
                    + ((l & 7) + ((l & 16) ? 8 : 0) + wn * 16) * S_ROWB
                    + ((l & 8) ? 16 : 0);

    float fah[8], iah[8];
#pragma unroll
    for (int p = 0; p < 8; p++) { fah[p] = 0.f; iah[p] = 0.f; }

    // double-buffered fragment registers
    u32 AH[2][4], Fh[2][4], Ih[2][4];

#define LDFR(kc_, s_)                                                         \
    do {                                                                      \
        const u32 ko_ = (kc_) * 32;                                           \
        ldsm4(AH[s_][0], AH[s_][1], AH[s_][2], AH[s_][3], ab + ko_);          \
        ldsm4(Fh[s_][0], Fh[s_][1], Fh[s_][2], Fh[s_][3], wb + ko_);          \
        ldsm4(Ih[s_][0], Ih[s_][1], Ih[s_][2], Ih[s_][3], wb + S_WS + ko_);   \
    } while (0)

#define MMASET(s_)                                                            \
    do {                                                                      \
        mma16816(fah[0], fah[1], fah[2], fah[3],                              \
                 AH[s_][0], AH[s_][1], AH[s_][2], AH[s_][3], Fh[s_][0], Fh[s_][1]); \
        mma16816(fah[4], fah[5], fah[6], fah[7],                              \
                 AH[s_][0], AH[s_][1], AH[s_][2], AH[s_][3], Fh[s_][2], Fh[s_][3]); \
        mma16816(iah[0], iah[1], iah[2], iah[3],                              \
                 AH[s_][0], AH[s_][1], AH[s_][2], AH[s_][3], Ih[s_][0], Ih[s_][1]); \
        mma16816(iah[4], iah[5], iah[6], iah[7],                              \
                 AH[s_][0], AH[s_][1], AH[s_][2], AH[s_][3], Ih[s_][2], Ih[s_][3]); \
    } while (0)

#pragma unroll 1
    for (int it = 0; it < 4; it++) {
        const int buf = it & 1;
        CP_WAIT0();
        __syncthreads();          // tile `it` resident; prior tile's readers done

        if (it < 3) {             // prefetch tile it+1 into the other buffer
            load_tile(it + 1, sm0 + (u32)(buf ^ 1) * S_BUF);
            CP_COMMIT();
        }

        const u32 ab = abase + (u32)buf * S_BUF;
        const u32 wb = wbase + (u32)buf * S_BUF;

        LDFR(0, 0);
#pragma unroll
        for (int kc = 0; kc < 16; kc++) {
            const int s = kc & 1;
            if (kc < 15) LDFR(kc + 1, s ^ 1);
            MMASET(s);
        }
    }

    // ---- epilogue: gates + cell update + re-split ----
#pragma unroll
    for (int p = 0; p < 8; p++) {
        const int j  = p >> 2;
        const int r  = (p >> 1) & 1;
        const int cc = p & 1;
        const int b  = M0 + wm * 16 + qr + r * 8;
        const int n  = N0 + wn * 16 + j * 8 + qc + cc;
        const int idx = j * 4 + r * 2 + cc;
        const float f  = sigmoidf_(fah[idx] + hGf[p]);
        const float ii = sigmoidf_(iah[idx] + hGi[p]);
        const float cn = hSc[p] * ii + hCo[p] * f;
        const __nv_bfloat16 hh = __float2bfloat16(cn);
        coh[(size_t)b * HH + n] = hh;
        clo[(size_t)b * HH + n] = __float2bfloat16(cn - __bfloat162float(hh));
    }
#undef LDFR
#undef MMASET
}

// ---------------- kernel: final o-gate + hidden (runs once; full 3-term) ----------------
__global__ __launch_bounds__(256)
void final_o_kernel(const int* __restrict__ x) {
    const __nv_bfloat16* __restrict__ cih = g_cst[1][0];   // c_prev (written t=510)
    const __nv_bfloat16* __restrict__ cil = g_cst[1][1];
    const __nv_bfloat16* __restrict__ lih = g_cst[0][0];   // c_last (written t=511)
    const __nv_bfloat16* __restrict__ lil = g_cst[0][1];

    extern __shared__ __align__(16) char dynsm[];
    __shared__ int cls_s[64];

    const int tid = threadIdx.x;
    const int M0  = blockIdx.y * 64;
    const int N0  = blockIdx.x * 32;
    if (tid < 64) cls_s[tid] = x[(M0 + tid) * SS + (SS - 1)];

    const int l   = tid & 31;
    const int wid = tid >> 5;
    const int wm  = wid >> 1;
    const int wn  = wid & 1;

    const int ar0 = tid >> 3;
    const int ar1 = (tid + 256) >> 3;
    const int ao  = tid & 7;
    const size_t sA0 = (size_t)(M0 + ar0) * HH + ao * 8;
    const size_t sA1 = (size_t)(M0 + ar1) * HH + ao * 8;
    const u32 dA0 = ar0 * ROWF + ao * 16;
    const u32 dA1 = ar1 * ROWF + ao * 16;
    const int wrow = tid >> 3;
    const size_t sW = (size_t)(N0 + wrow) * HH + ao * 8;
    const u32 dW = wrow * ROWF + ao * 16;

    const u32 sm0 = smem_u32(dynsm);

    cpa16(sm0 + dA0,         cih + sA0);
    cpa16(sm0 + dA1,         cih + sA1);
    cpa16(sm0 + F_ALO + dA0, cil + sA0);
    cpa16(sm0 + F_ALO + dA1, cil + sA1);
    cpa16(sm0 + F_W + dW,        g_Wsp[4] + sW);
    cpa16(sm0 + F_W + F_WS + dW, g_Wsp[5] + sW);
    CP_COMMIT();

    __syncthreads();

    const int qr = l >> 2;
    const int qc = (l & 3) * 2;
    float hGo[8], hCl[8];
#pragma unroll
    for (int p = 0; p < 8; p++) {
        const int j  = p >> 2;
        const int r  = (p >> 1) & 1;
        const int cc = p & 1;
        const int bl = wm * 16 + qr + r * 8;
        const int b  = M0 + bl;
        const int n  = N0 + wn * 16 + j * 8 + qc + cc;
        const int cls = cls_s[bl];
        hGo[p] = __ldg(&g_Go[cls * HH + n]);
        hCl[p] = __bfloat162float(__ldg(&lih[(size_t)b * HH + n]))
               + __bfloat162float(__ldg(&lil[(size_t)b * HH + n]));
    }

    const u32 abase = sm0 + (wm * 16 + (l & 15)) * ROWF + ((l >> 4) & 1) * 16;
    const u32 wbase = sm0 + F_W
                    + ((l & 7) + ((l & 16) ? 8 : 0) + wn * 16) * ROWF
                    + ((l & 8) ? 16 : 0);

    float oa[8];
#pragma unroll
    for (int p = 0; p < 8; p++) oa[p] = 0.f;

#pragma unroll 1
    for (int it = 0; it < 16; it++) {
        const int buf = it & 1;
        CP_WAIT0();
        __syncthreads();
        if (it < 15) {
            const size_t kadv = (size_t)(it + 1) * 64;
            const u32 db = (buf ^ 1) * F_BUF;
            cpa16(sm0 + db + dA0,         cih + sA0 + kadv);
            cpa16(sm0 + db + dA1,         cih + sA1 + kadv);
            cpa16(sm0 + db + F_ALO + dA0, cil + sA0 + kadv);
            cpa16(sm0 + db + F_ALO + dA1, cil + sA1 + kadv);
            cpa16(sm0 + db + F_W + dW,        g_Wsp[4] + sW + kadv);
            cpa16(sm0 + db + F_W + F_WS + dW, g_Wsp[5] + sW + kadv);
            CP_COMMIT();
        }

        const u32 ab = abase + buf * F_BUF;
        const u32 wb = wbase + buf * F_BUF;
#pragma unroll
        for (int kc = 0; kc < 4; kc++) {
            const u32 ko = kc * 32;
            u32 ah0, ah1, ah2, ah3, al0, al1, al2, al3;
            ldsm4(ah0, ah1, ah2, ah3, ab + ko);
            ldsm4(al0, al1, al2, al3, ab + F_ALO + ko);
            u32 o0, o1, o2, o3, q0, q1, q2, q3;
            ldsm4(o0, o1, o2, o3, wb + ko);
            ldsm4(q0, q1, q2, q3, wb + F_WS + ko);
            mma16816(oa[0], oa[1], oa[2], oa[3], ah0, ah1, ah2, ah3, o0, o1);
            mma16816(oa[0], oa[1], oa[2], oa[3], ah0, ah1, ah2, ah3, q0, q1);
            mma16816(oa[0], oa[1], oa[2], oa[3], al0, al1, al2, al3, o0, o1);
            mma16816(oa[4], oa[5], oa[6], oa[7], ah0, ah1, ah2, ah3, o2, o3);
            mma16816(oa[4], oa[5], oa[6], oa[7], ah0, ah1, ah2, ah3, q2, q3);
            mma16816(oa[4], oa[5], oa[6], oa[7], al0, al1, al2, al3, o2, o3);
        }
    }

#pragma unroll
    for (int p = 0; p < 8; p++) {
        const int j  = p >> 2;
        const int r  = (p >> 1) & 1;
        const int cc = p & 1;
        const int b  = M0 + wm * 16 + qr + r * 8;
        const int n  = N0 + wn * 16 + j * 8 + qc + cc;
        const int idx = j * 4 + r * 2 + cc;
        const float o = sigmoidf_(oa[idx] + hGo[p]);
        g_h[(size_t)b * HH + n] = tanhf(hCl[p]) * o;
    }
}

// ---------------- kernel: logits + log_softmax ----------------
__global__ __launch_bounds__(128)
void logits_kernel(const float* __restrict__ Wph, const float* __restrict__ bp,
                   float* __restrict__ out) {
    const int b = blockIdx.x;
    const int j = threadIdx.x;

    __shared__ __align__(16) float h_s[HH];
    __shared__ float red[128];

    const float4* hv  = reinterpret_cast<const float4*>(&g_h[(size_t)b * HH]);
    float4*       hs4 = reinterpret_cast<float4*>(h_s);
    for (int i = j; i < HH / 4; i += 128) hs4[i] = hv[i];
    __syncthreads();

    float acc = 0.f;
    const float4* w4 = reinterpret_cast<const float4*>(&Wph[(size_t)j * HH]);
#pragma unroll 4
    for (int k = 0; k < HH / 4; k++) {
        const float4 w = w4[k];
        const float4 h = hs4[k];
        acc = fmaf(h.x, w.x, acc);
        acc = fmaf(h.y, w.y, acc);
        acc = fmaf(h.z, w.z, acc);
        acc = fmaf(h.w, w.w, acc);
    }
    const float p = acc + bp[j];

    red[j] = p;
    __syncthreads();
    for (int s2 = 64; s2 > 0; s2 >>= 1) {
        if (j < s2) red[j] = fmaxf(red[j], red[j + s2]);
        __syncthreads();
    }
    const float mx = red[0];
    __syncthreads();
    red[j] = expf(p - mx);
    __syncthreads();
    for (int s2 = 64; s2 > 0; s2 >>= 1) {
        if (j < s2) red[j] += red[j + s2];
        __syncthreads();
    }
    const float lse = logf(red[0]) + mx;
    out[b * CC + j] = p - lse;
}

// ---------------- launcher ----------------
extern "C" void kernel_launch(void* const* d_in, const int* in_sizes, int n_in,
                              void* d_out, int out_size) {
    const int*   x   = (const int*)  d_in[0];
    const float* emb = (const float*)d_in[1];
    const float* Wcx = (const float*)d_in[2];
    const float* bc  = (const float*)d_in[3];
    const float* Wix = (const float*)d_in[4];
    const float* Wih = (const float*)d_in[5];
    const float* bi  = (const float*)d_in[6];
    const float* Wfx = (const float*)d_in[7];
    const float* Wfh = (const float*)d_in[8];
    const float* bf  = (const float*)d_in[9];
    const float* Wox = (const float*)d_in[10];
    const float* Woh = (const float*)d_in[11];
    const float* bo  = (const float*)d_in[12];
    const float* Wph = (const float*)d_in[13];
    const float* bp  = (const float*)d_in[14];
    float* out = (float*)d_out;

    cudaFuncSetAttribute(step_kernel,
                         cudaFuncAttributeMaxDynamicSharedMemorySize, SMEM_STEP);
    cudaFuncSetAttribute(final_o_kernel,
                         cudaFuncAttributeMaxDynamicSharedMemorySize, SMEM_FIN);

    wsplit_kernel<<<(HH * HH + 255) / 256, 256>>>(Wfh, Wih, Woh);
    tab_kernel<<<dim3(32, 4), 256>>>(emb, Wfx, Wix, Wox, Wcx, bf, bi, bo, bc);

    const int zgrid = (CZ_FLOAT4 + 255) / 256;
    zero_kernel<<<zgrid, 256>>>();

    for (int t = 0; t < SS; t++) {
        step_kernel<<<dim3(32, 4), 256, SMEM_STEP>>>(x, t);
    }

    final_o_kernel<<<dim3(32, 4), 256, SMEM_FIN>>>(x);
    logits_kernel<<<BB, 128>>>(Wph, bp, out);
}